// round 15
// baseline (speedup 1.0000x reference)
#include <cuda_runtime.h>

#define NH 128
#define NI 64
#define NO 10
#define NB 128
#define S_MAX 2048
#define NPROD 320   // producer CTAs

// 128 MiB scratch for the precomputed input projection xW[S,B,H].
__device__ __align__(16) float g_xw[(size_t)S_MAX * NB * NH];
// per-timestep completion flags (zero-init at load; stay 1 across graph
// replays -- benign, since xW values are identical every replay)
__device__ int g_flag[S_MAX];

// ---- packed f32x2 helpers (sm_100+ PTX) ----
__device__ __forceinline__ unsigned long long ffma2(unsigned long long a,
                                                    unsigned long long b,
                                                    unsigned long long c) {
    unsigned long long d;
    asm("fma.rn.f32x2 %0, %1, %2, %3;" : "=l"(d) : "l"(a), "l"(b), "l"(c));
    return d;
}
__device__ __forceinline__ unsigned long long packf2(float lo, float hi) {
    unsigned long long r;
    asm("mov.b64 %0, {%1, %2};" : "=l"(r) : "f"(lo), "f"(hi));
    return r;
}
__device__ __forceinline__ float2 unpackf2(unsigned long long v) {
    float2 f;
    asm("mov.b64 {%0, %1}, %2;" : "=f"(f.x), "=f"(f.y) : "l"(v));
    return f;
}
__device__ __forceinline__ int ld_acq(const int* p) {
    int v;
    asm volatile("ld.acquire.gpu.global.u32 %0, [%1];" : "=r"(v) : "l"(p) : "memory");
    return v;
}
__device__ __forceinline__ void st_rel(int* p, int v) {
    asm volatile("st.release.gpu.global.u32 [%0], %1;" :: "l"(p), "r"(v) : "memory");
}

// ============================================================
// One fat kernel. grid = NB + NPROD CTAs, block = 128.
//  bid <  NB : scan CTA  (R10 body + flag-gated xw prefetch)
//  bid >= NB : producer CTA (grid-stride s-tiles, ascending)
// Producers fill the scan's ~83% idle issue slots (2 CTAs/SM
// co-residency: 24.6K regs + 37KB smem per CTA).
// ============================================================
__global__ void __launch_bounds__(128, 1) rnn_fat_kernel(
    const float* __restrict__ x,    // [S, B, NI]
    const float* __restrict__ Wxh,  // [NI, NH]
    const float* __restrict__ Whh,  // [NH, NH]
    const float* __restrict__ Why,  // [NH, NO]
    const float* __restrict__ bh,   // [NH]
    const float* __restrict__ by,   // [NO]
    float* __restrict__ out,        // logits [B,NO] then h [S,B,NH]
    int seq)
{
    const int tid = threadIdx.x;

    __shared__ __align__(16) float hbuf[2][NH];        // scan: parity h
    __shared__ __align__(16) float part[2][4][NH];     // scan: partials
    __shared__ __align__(16) float xs[NB * NI];        // producer: x tile (32KB)

    if (blockIdx.x >= NB) {
        // ================= PRODUCER =================
        const int pc = blockIdx.x - NB;
        const int P  = gridDim.x - NB;
        const int j  = tid;

        unsigned long long w2[NI / 2];
#pragma unroll
        for (int m = 0; m < NI / 2; m++)
            w2[m] = packf2(Wxh[(2 * m) * NH + j], Wxh[(2 * m + 1) * NH + j]);
        const float biasj = bh[j];

        for (int s = pc; s < seq; s += P) {
            __syncthreads();  // previous tile fully consumed
            const float4* xin =
                reinterpret_cast<const float4*>(x + (long long)s * NB * NI);
            float4* xs4 = reinterpret_cast<float4*>(xs);
#pragma unroll
            for (int i = tid; i < NB * NI / 4; i += 128) xs4[i] = xin[i];
            __syncthreads();

            float* orow = g_xw + (long long)s * NB * NH + j;
#pragma unroll 4
            for (int r = 0; r < NB; r++) {
                const ulonglong2* xr =
                    reinterpret_cast<const ulonglong2*>(xs + r * NI);
                unsigned long long a0 = 0ull, a1 = 0ull, a2 = 0ull, a3 = 0ull;
#pragma unroll
                for (int m = 0; m < NI / 4; m++) {
                    ulonglong2 xv = xr[m];  // broadcast LDS.128
                    if (m & 1) { a2 = ffma2(xv.x, w2[2 * m], a2); a3 = ffma2(xv.y, w2[2 * m + 1], a3); }
                    else       { a0 = ffma2(xv.x, w2[2 * m], a0); a1 = ffma2(xv.y, w2[2 * m + 1], a1); }
                }
                float2 f0 = unpackf2(a0), f1 = unpackf2(a1),
                       f2 = unpackf2(a2), f3 = unpackf2(a3);
                orow[r * NH] = ((f0.x + f0.y) + (f1.x + f1.y)) +
                               ((f2.x + f2.y) + (f3.x + f3.y)) + biasj;
            }
            __threadfence();   // each thread's STGs ordered before its bar
            __syncthreads();
            if (tid == 0) st_rel(&g_flag[s], 1);
        }
        return;
    }

    // ================= SCAN (R10 body + flag gate) =================
    const int b = blockIdx.x;
    const int w = tid >> 5;   // warp = K-slice index
    const int l = tid & 31;

    unsigned long long wp[4][16];
#pragma unroll
    for (int c = 0; c < 4; c++) {
        const int col = 4 * l + c;
#pragma unroll
        for (int kk = 0; kk < 16; kk++) {
            const int k = 32 * w + 2 * kk;
            wp[c][kk] = packf2(Whh[k * NH + col], Whh[(k + 1) * NH + col]);
        }
    }
    const float bias = bh[tid];
    hbuf[0][tid] = 0.0f;

    // xw prefetch ring (depth 4), flag-gated
    const float* xwb = g_xw + (long long)b * NH + tid;
    float xq[4];
    int   fr[4];
#pragma unroll
    for (int q = 0; q < 4; q++) {
        if (q < seq) {
            while (ld_acq(&g_flag[q]) == 0) __nanosleep(64);
            xq[q] = xwb[(long long)q * NB * NH];
        } else xq[q] = 0.0f;
        fr[q] = (q + 4 < seq) ? ld_acq(&g_flag[q + 4]) : 1;
    }

    float* h_out = out + NB * NO;
    __syncthreads();

#pragma unroll 4
    for (int t = 0; t < seq; t++) {
        const int pb = t & 1;

        // ---- batched load of OWN warp's h slice (8 broadcast LDS.128) ----
        ulonglong2 hv[8];
        const ulonglong2* h2 =
            reinterpret_cast<const ulonglong2*>(&hbuf[pb][32 * w]);
#pragma unroll
        for (int m = 0; m < 8; m++) hv[m] = h2[m];

        // ---- 32-term partials for columns 4l..4l+3 (64 FFMA2) ----
        unsigned long long a0 = 0ull, a1 = 0ull, a2 = 0ull, a3 = 0ull;
#pragma unroll
        for (int m = 0; m < 8; m++) {
            a0 = ffma2(hv[m].x, wp[0][2 * m], a0);
            a0 = ffma2(hv[m].y, wp[0][2 * m + 1], a0);
            a1 = ffma2(hv[m].x, wp[1][2 * m], a1);
            a1 = ffma2(hv[m].y, wp[1][2 * m + 1], a1);
            a2 = ffma2(hv[m].x, wp[2][2 * m], a2);
            a2 = ffma2(hv[m].y, wp[2][2 * m + 1], a2);
            a3 = ffma2(hv[m].x, wp[3][2 * m], a3);
            a3 = ffma2(hv[m].y, wp[3][2 * m + 1], a3);
        }
        float2 f0 = unpackf2(a0), f1 = unpackf2(a1),
               f2 = unpackf2(a2), f3 = unpackf2(a3);
        float4 pr = make_float4(f0.x + f0.y, f1.x + f1.y,
                                f2.x + f2.y, f3.x + f3.y);
        *reinterpret_cast<float4*>(&part[pb][w][4 * l]) = pr;  // conflict-free

        // xw consume + flag-gated refill (acquire flag prefetched 4 steps
        // ahead -> fast path is ISETP+BRA; spin is cold after warmup)
        const float xwv = xq[t & 3];
        if (t + 4 < seq) {
            if (fr[t & 3] != 1) {
                int f;
                do { f = ld_acq(&g_flag[t + 4]); if (f == 0) __nanosleep(64); } while (f == 0);
                fr[t & 3] = f;
            }
            xq[t & 3] = xwb[(long long)(t + 4) * NB * NH];
            fr[t & 3] = (t + 8 < seq) ? ld_acq(&g_flag[t + 8]) : 1;
        }

        __syncthreads();

        // ---- reduce 4 partials for OWN column tid ----
        float v = ((part[pb][0][tid] + part[pb][1][tid]) +
                   (part[pb][2][tid] + part[pb][3][tid])) + xwv + bias;

        // tanh: exp2 + fast reciprocal (denominator in [1,2] -> ~2 ulp).
        float a = fabsf(v);
        float e = __expf(-2.0f * a);
        float r = __fdividef(1.0f - e, 1.0f + e);
        float h = copysignf(r, v);

        h_out[((long long)t * NB + b) * NH + tid] = h;  // coalesced 512 B
        hbuf[pb ^ 1][tid] = h;   // own-warp slice; next step reads own slice only
        __syncwarp();
    }

    __syncthreads();
    // ---- logits = h_last @ Why + by ----
    if (tid < NO) {
        float acc = by[tid];
#pragma unroll 8
        for (int k = 0; k < NH; k++)
            acc = fmaf(hbuf[seq & 1][k], Why[k * NO + tid], acc);
        out[b * NO + tid] = acc;
    }
}

extern "C" void kernel_launch(void* const* d_in, const int* in_sizes, int n_in,
                              void* d_out, int out_size) {
    const float* x   = (const float*)d_in[0];
    const float* Wxh = (const float*)d_in[1];
    const float* Whh = (const float*)d_in[2];
    const float* Why = (const float*)d_in[3];
    const float* bh  = (const float*)d_in[4];
    const float* by  = (const float*)d_in[5];
    float* out = (float*)d_out;

    int seq = in_sizes[0] / (NB * NI);  // 2048
    if (seq > S_MAX) seq = S_MAX;

    rnn_fat_kernel<<<NB + NPROD, 128>>>(x, Wxh, Whh, Why, bh, by, out, seq);
}

// round 16
// speedup vs baseline: 1.7010x; 1.7010x over previous
#include <cuda_runtime.h>

#define NH 128
#define NI 64
#define NO 10
#define NB 128
#define S_MAX 2048

// 128 MiB scratch for the precomputed input projection xW[S,B,H].
__device__ __align__(16) float g_xw[(size_t)S_MAX * NB * NH];

// ---- packed f32x2 helpers (sm_100+ PTX) ----
__device__ __forceinline__ unsigned long long ffma2(unsigned long long a,
                                                    unsigned long long b,
                                                    unsigned long long c) {
    unsigned long long d;
    asm("fma.rn.f32x2 %0, %1, %2, %3;" : "=l"(d) : "l"(a), "l"(b), "l"(c));
    return d;
}
__device__ __forceinline__ unsigned long long packf2(float lo, float hi) {
    unsigned long long r;
    asm("mov.b64 %0, {%1, %2};" : "=l"(r) : "f"(lo), "f"(hi));
    return r;
}
__device__ __forceinline__ float2 unpackf2(unsigned long long v) {
    float2 f;
    asm("mov.b64 {%0, %1}, %2;" : "=f"(f.x), "=f"(f.y) : "l"(v));
    return f;
}

// ============================================================
// K1 (persistent, 1 wave, double-buffered):
//   xW[s,b,j] = x[s,b,:] @ Wxh[:,j] + bh[j]
// grid = 148 CTAs (exactly one wave), block = 256.
// Thread: column pair (2jj, 2jj+1), jj = tid&63; row group p = tid>>6.
// Tile = (s, 64 batch rows). While computing tile i from smem buf,
// the next tile's x (4 float4/thread) is in flight in registers;
// STS into buf^1 after compute. Two barriers/tile vs ~4100 cyc of
// fma-bound compute -> x DRAM latency fully hidden.
// ============================================================
__global__ void __launch_bounds__(256, 1) xw_gemm_kernel(
    const float* __restrict__ x, const float* __restrict__ Wxh,
    const float* __restrict__ bh, int seq)
{
    const int tid = threadIdx.x;
    const int jj  = tid & 63;   // column pair index
    const int p   = tid >> 6;   // row group 0..3
    const int c0  = 2 * jj;

    // weights for 2 columns, packed by k-pairs (128 regs)
    unsigned long long w2[2][NI / 2];
#pragma unroll
    for (int ci = 0; ci < 2; ci++) {
        const int col = c0 + ci;
#pragma unroll
        for (int m = 0; m < NI / 2; m++)
            w2[ci][m] = packf2(Wxh[(2 * m) * NH + col],
                               Wxh[(2 * m + 1) * NH + col]);
    }
    const float2 bias2 = make_float2(bh[c0], bh[c0 + 1]);

    __shared__ __align__(16) float xs[2][64 * NI];  // 2 x 16 KB

    const int ntiles = 2 * seq;       // (s, half) tiles of 64 batch rows
    const int stride = gridDim.x;

    int tile = blockIdx.x;
    // preload first tile into buffer 0
    if (tile < ntiles) {
        const float4* xin = reinterpret_cast<const float4*>(
            x + ((long long)(tile >> 1) * NB + (tile & 1) * 64) * NI);
        float4* d = reinterpret_cast<float4*>(xs[0]);
#pragma unroll
        for (int q = 0; q < 4; q++) d[tid + 256 * q] = xin[tid + 256 * q];
    }
    __syncthreads();

    int buf = 0;
    for (; tile < ntiles; tile += stride) {
        const int nxt = tile + stride;

        // ---- issue next tile's loads (latency hidden under compute) ----
        float4 pf[4];
        if (nxt < ntiles) {
            const float4* xin = reinterpret_cast<const float4*>(
                x + ((long long)(nxt >> 1) * NB + (nxt & 1) * 64) * NI);
#pragma unroll
            for (int q = 0; q < 4; q++) pf[q] = xin[tid + 256 * q];
        }

        // ---- compute current tile ----
        const int s  = tile >> 1;
        const int bb = (tile & 1) * 64;
        float* orow = g_xw + ((long long)s * NB + bb) * NH;
#pragma unroll 4
        for (int r = p; r < 64; r += 4) {
            const ulonglong2* xr =
                reinterpret_cast<const ulonglong2*>(xs[buf] + r * NI);
            unsigned long long a00 = 0ull, a01 = 0ull;  // col c0
            unsigned long long a10 = 0ull, a11 = 0ull;  // col c0+1
#pragma unroll
            for (int m = 0; m < NI / 4; m++) {
                ulonglong2 xv = xr[m];  // broadcast LDS.128 (same row per warp)
                a00 = ffma2(xv.x, w2[0][2 * m], a00);
                a01 = ffma2(xv.y, w2[0][2 * m + 1], a01);
                a10 = ffma2(xv.x, w2[1][2 * m], a10);
                a11 = ffma2(xv.y, w2[1][2 * m + 1], a11);
            }
            float2 f00 = unpackf2(a00), f01 = unpackf2(a01);
            float2 f10 = unpackf2(a10), f11 = unpackf2(a11);
            float2 o = make_float2((f00.x + f00.y) + (f01.x + f01.y) + bias2.x,
                                   (f10.x + f10.y) + (f11.x + f11.y) + bias2.y);
            *reinterpret_cast<float2*>(&orow[r * NH + c0]) = o;  // STG.64
        }

        __syncthreads();            // everyone done reading buf^1's old data
        if (nxt < ntiles) {
            float4* d = reinterpret_cast<float4*>(xs[buf ^ 1]);
#pragma unroll
            for (int q = 0; q < 4; q++) d[tid + 256 * q] = pf[q];
        }
        __syncthreads();            // new buf^1 visible before next compute
        buf ^= 1;
    }
}

// ============================================================
// K2 (R10 verbatim): sequential scan with K-split partial exchange.
// grid = NB (1 chain per CTA/SM), block = 128.
// Warp w owns columns [32w,32w+32) AND K-slice [32w,32w+32).
// tanh via exp + __fdividef (MUFU.RCP; denominator in [1,2] -> ~2 ulp).
// ============================================================
__global__ void __launch_bounds__(NH, 1) rnn_scan_kernel(
    const float* __restrict__ Whh, const float* __restrict__ Why,
    const float* __restrict__ bh, const float* __restrict__ by,
    float* __restrict__ out, int seq)
{
    const int b   = blockIdx.x;
    const int tid = threadIdx.x;
    const int w   = tid >> 5;   // warp = K-slice index
    const int l   = tid & 31;

    // Weights: wp[c][kk] packs Whh[k][4l+c] for k-pair (32w+2kk, 32w+2kk+1).
    unsigned long long wp[4][16];
#pragma unroll
    for (int c = 0; c < 4; c++) {
        const int col = 4 * l + c;
#pragma unroll
        for (int kk = 0; kk < 16; kk++) {
            const int k = 32 * w + 2 * kk;
            wp[c][kk] = packf2(Whh[k * NH + col], Whh[(k + 1) * NH + col]);
        }
    }
    const float bias = bh[tid];

    __shared__ __align__(16) float hbuf[2][NH];        // parity-swapped h
    __shared__ __align__(16) float part[2][4][NH];     // double-buffered partials
    hbuf[0][tid] = 0.0f;

    // xw prefetch ring (depth 4) for OWN column tid
    const float* xwb = g_xw + (long long)b * NH + tid;
    float xq[4];
#pragma unroll
    for (int q = 0; q < 4; q++)
        xq[q] = (q < seq) ? xwb[(long long)q * NB * NH] : 0.0f;

    float* h_out = out + NB * NO;
    __syncthreads();

#pragma unroll 4
    for (int t = 0; t < seq; t++) {
        const int pb = t & 1;

        // ---- batched load of OWN warp's h slice (8 broadcast LDS.128) ----
        ulonglong2 hv[8];
        const ulonglong2* h2 =
            reinterpret_cast<const ulonglong2*>(&hbuf[pb][32 * w]);
#pragma unroll
        for (int m = 0; m < 8; m++) hv[m] = h2[m];

        // ---- 32-term partials for columns 4l..4l+3 (64 FFMA2) ----
        unsigned long long a0 = 0ull, a1 = 0ull, a2 = 0ull, a3 = 0ull;
#pragma unroll
        for (int m = 0; m < 8; m++) {
            a0 = ffma2(hv[m].x, wp[0][2 * m], a0);
            a0 = ffma2(hv[m].y, wp[0][2 * m + 1], a0);
            a1 = ffma2(hv[m].x, wp[1][2 * m], a1);
            a1 = ffma2(hv[m].y, wp[1][2 * m + 1], a1);
            a2 = ffma2(hv[m].x, wp[2][2 * m], a2);
            a2 = ffma2(hv[m].y, wp[2][2 * m + 1], a2);
            a3 = ffma2(hv[m].x, wp[3][2 * m], a3);
            a3 = ffma2(hv[m].y, wp[3][2 * m + 1], a3);
        }
        float2 f0 = unpackf2(a0), f1 = unpackf2(a1),
               f2 = unpackf2(a2), f3 = unpackf2(a3);
        float4 pr = make_float4(f0.x + f0.y, f1.x + f1.y,
                                f2.x + f2.y, f3.x + f3.y);
        *reinterpret_cast<float4*>(&part[pb][w][4 * l]) = pr;  // conflict-free

        // xw consume + refill (covers DRAM latency across 4 steps)
        const float xwv = xq[t & 3];
        if (t + 4 < seq) xq[t & 3] = xwb[(long long)(t + 4) * NB * NH];

        __syncthreads();

        // ---- reduce 4 partials for OWN column tid ----
        float v = ((part[pb][0][tid] + part[pb][1][tid]) +
                   (part[pb][2][tid] + part[pb][3][tid])) + xwv + bias;

        // tanh: exp2 + fast reciprocal (denominator in [1,2] -> ~2 ulp).
        float a = fabsf(v);
        float e = __expf(-2.0f * a);
        float r = __fdividef(1.0f - e, 1.0f + e);
        float h = copysignf(r, v);

        h_out[((long long)t * NB + b) * NH + tid] = h;  // coalesced 512 B
        hbuf[pb ^ 1][tid] = h;   // own-warp slice; next step reads own slice only
        __syncwarp();
    }

    __syncthreads();
    // ---- logits = h_last @ Why + by ----
    if (tid < NO) {
        float acc = by[tid];
#pragma unroll 8
        for (int k = 0; k < NH; k++)
            acc = fmaf(hbuf[seq & 1][k], Why[k * NO + tid], acc);
        out[b * NO + tid] = acc;
    }
}

extern "C" void kernel_launch(void* const* d_in, const int* in_sizes, int n_in,
                              void* d_out, int out_size) {
    const float* x   = (const float*)d_in[0];
    const float* Wxh = (const float*)d_in[1];
    const float* Whh = (const float*)d_in[2];
    const float* Why = (const float*)d_in[3];
    const float* bh  = (const float*)d_in[4];
    const float* by  = (const float*)d_in[5];
    float* out = (float*)d_out;

    int seq = in_sizes[0] / (NB * NI);  // 2048
    if (seq > S_MAX) seq = S_MAX;

    int ntiles = 2 * seq;
    int grid1 = ntiles < 148 ? ntiles : 148;   // exactly one wave
    xw_gemm_kernel<<<grid1, 256>>>(x, Wxh, bh, seq);
    rnn_scan_kernel<<<NB, NH>>>(Whh, Why, bh, by, out, seq);
}